// round 1
// baseline (speedup 1.0000x reference)
#include <cuda_runtime.h>
#include <cuda_bf16.h>
#include <mma.h>

using namespace nvcuda;

#define NTOK 4096
#define DIM 256
#define NHEAD 8
#define HDD (NHEAD*DIM*DIM)

// ---------------- scratch (device globals; no cudaMalloc allowed) ----------------
__device__ __nv_bfloat16 g_xln [NTOK*DIM];
__device__ __nv_bfloat16 g_wqkv[3*HDD];
__device__ __nv_bfloat16 g_wo  [DIM*NHEAD*DIM];
__device__ __nv_bfloat16 g_wff [DIM*DIM];
__device__ __nv_bfloat16 g_qkv [3ULL*NHEAD*NTOK*DIM];
__device__ __nv_bfloat16 g_cat [(size_t)NTOK*NHEAD*DIM];
__device__ float         g_xout[NTOK*DIM];
__device__ __nv_bfloat16 g_xln2[NTOK*DIM];

// ---------------- layernorm: fp32 in -> bf16 out ----------------
__global__ void ln_kernel(const float* __restrict__ x, const float* __restrict__ g,
                          const float* __restrict__ b, __nv_bfloat16* __restrict__ out)
{
    int row = blockIdx.x;
    int t = threadIdx.x;
    float v = x[row*DIM + t];
    float sum = v, sq = v*v;
    #pragma unroll
    for (int o = 16; o > 0; o >>= 1) {
        sum += __shfl_xor_sync(0xffffffffu, sum, o);
        sq  += __shfl_xor_sync(0xffffffffu, sq,  o);
    }
    __shared__ float s1[8], s2[8];
    if ((t & 31) == 0) { s1[t>>5] = sum; s2[t>>5] = sq; }
    __syncthreads();
    __shared__ float smu, srstd;
    if (t == 0) {
        float S = 0.f, Q = 0.f;
        #pragma unroll
        for (int i = 0; i < 8; i++) { S += s1[i]; Q += s2[i]; }
        float m = S * (1.0f/DIM);
        smu = m;
        srstd = rsqrtf(Q * (1.0f/DIM) - m*m + 1e-5f);
    }
    __syncthreads();
    out[row*DIM + t] = __float2bfloat16((v - smu) * srstd * g[t] + b[t]);
}

// ---------------- fp32 -> bf16 weight conversion ----------------
__global__ void cvt_kernel(const float* __restrict__ src, __nv_bfloat16* __restrict__ dst, int n)
{
    int i = blockIdx.x * blockDim.x + threadIdx.x;
    if (i < n) dst[i] = __float2bfloat16(src[i]);
}

// ---------------- generic 128x128 bf16 WMMA GEMM: C = A @ B^T (+epilogue) -------
// A: [M, K] bf16 row-major, B: [Ncols, K] bf16 row-major (used transposed)
// EPI 0: QKV scatter (bias + q-scale, bf16 out), EPI 1: bias + residual, fp32 out
template<int EPI>
__global__ void gemm_kernel(const __nv_bfloat16* __restrict__ A,
                            const __nv_bfloat16* __restrict__ B,
                            int K,
                            const float* __restrict__ b0,
                            const float* __restrict__ b1,
                            const float* __restrict__ b2,
                            const float* __restrict__ res,
                            float* __restrict__ outf,
                            __nv_bfloat16* __restrict__ outb)
{
    extern __shared__ char smem[];
    __nv_bfloat16* As = (__nv_bfloat16*)smem;          // [128][16]
    __nv_bfloat16* Bs = As + 128*16;                   // [128][16]
    float* Cs = (float*)smem;                          // [128][132] (aliases As/Bs)

    int bm = blockIdx.x * 128;
    int bn = blockIdx.y * 128;
    int t = threadIdx.x;
    int w = t >> 5;
    int wr = w & 3, wc = w >> 2;   // 4x2 warp grid, each warp 32x64

    wmma::fragment<wmma::accumulator,16,16,16,float> acc[2][4];
    #pragma unroll
    for (int i = 0; i < 2; i++)
        #pragma unroll
        for (int j = 0; j < 4; j++)
            wmma::fill_fragment(acc[i][j], 0.0f);

    int lr = t >> 1;
    int lc = (t & 1) << 3;

    for (int k0 = 0; k0 < K; k0 += 16) {
        *(uint4*)&As[lr*16 + lc] = *(const uint4*)&A[(size_t)(bm+lr)*K + k0 + lc];
        *(uint4*)&Bs[lr*16 + lc] = *(const uint4*)&B[(size_t)(bn+lr)*K + k0 + lc];
        __syncthreads();
        wmma::fragment<wmma::matrix_a,16,16,16,__nv_bfloat16,wmma::row_major> af[2];
        #pragma unroll
        for (int i = 0; i < 2; i++)
            wmma::load_matrix_sync(af[i], As + (wr*32 + i*16)*16, 16);
        #pragma unroll
        for (int j = 0; j < 4; j++) {
            wmma::fragment<wmma::matrix_b,16,16,16,__nv_bfloat16,wmma::col_major> bfr;
            wmma::load_matrix_sync(bfr, Bs + (wc*64 + j*16)*16, 16);
            #pragma unroll
            for (int i = 0; i < 2; i++)
                wmma::mma_sync(acc[i][j], af[i], bfr, acc[i][j]);
        }
        __syncthreads();
    }

    #pragma unroll
    for (int i = 0; i < 2; i++)
        #pragma unroll
        for (int j = 0; j < 4; j++)
            wmma::store_matrix_sync(&Cs[(wr*32 + i*16)*132 + wc*64 + j*16], acc[i][j],
                                    132, wmma::mem_row_major);
    __syncthreads();

    for (int idx = t; idx < 128*128; idx += 256) {
        int r = idx >> 7, c = idx & 127;
        int n = bm + r, cc = bn + c;
        float v = Cs[r*132 + c];
        if (EPI == 0) {
            int which = cc >> 11;               // 0=q, 1=k, 2=v
            const float* bp = (which == 0) ? b0 : (which == 1) ? b1 : b2;
            v += bp[cc & 2047];
            if (which == 0) v *= 0.0625f;       // 1/sqrt(D), D=256
            int h = (cc >> 8) & 7;
            int e = cc & 255;
            outb[((size_t)which*NHEAD + h)*NTOK*DIM + (size_t)n*DIM + e] = __float2bfloat16(v);
        } else {
            v += b0[cc] + res[(size_t)n*DIM + cc];
            outf[(size_t)n*DIM + cc] = v;
        }
    }
}

// ---------------- fused biased/masked attention (no-max softmax) ----------------
// grid: (NHEAD, NTOK/64). Each block: 64 query rows of one head, full KV sweep.
// smem layout (dynamic): Qs 32K | Ks 32K | Vs 32K | Sb (64x72 f32) | Ps (64x72 bf16)
#define ATT_SMEM (64*256*2*3 + 64*72*4 + 64*72*2)

__global__ void attn_kernel(const float* __restrict__ spatial,
                            const float* __restrict__ edge,
                            const int* __restrict__ mask_idx)
{
    extern __shared__ char smem[];
    __nv_bfloat16* Qs = (__nv_bfloat16*)smem;
    __nv_bfloat16* Ks = Qs + 64*256;
    __nv_bfloat16* Vs = Ks + 64*256;
    float*         Sb = (float*)(Vs + 64*256);           // [64][72]
    __nv_bfloat16* Ps = (__nv_bfloat16*)(Sb + 64*72);    // [64][72]
    float*         Os = (float*)Ks;                      // epilogue alias [64][260]

    __shared__ int rmask[64], cmask[64];
    __shared__ float linv[64];

    int h  = blockIdx.x;
    int n0 = blockIdx.y * 64;
    int t  = threadIdx.x;
    int w  = t >> 5;
    int wr = w & 3, wc = w >> 2;

    const __nv_bfloat16* qh = g_qkv + (size_t)h*NTOK*DIM;
    const __nv_bfloat16* kh = g_qkv + (size_t)(NHEAD   + h)*NTOK*DIM;
    const __nv_bfloat16* vh = g_qkv + (size_t)(2*NHEAD + h)*NTOK*DIM;

    #pragma unroll
    for (int i = t; i < 64*32; i += 256) {
        int r = i >> 5, c = (i & 31) << 3;
        *(uint4*)&Qs[r*256 + c] = *(const uint4*)&qh[(size_t)(n0+r)*DIM + c];
    }
    if (t < 64) rmask[t] = mask_idx[n0 + t];

    wmma::fragment<wmma::accumulator,16,16,16,float> o[8];
    #pragma unroll
    for (int j = 0; j < 8; j++) wmma::fill_fragment(o[j], 0.0f);

    float lsum = 0.f;
    int er = t >> 2;            // exp row (4 threads/row)
    int ec = (t & 3) << 4;      // 16 cols per thread

    #pragma unroll 1
    for (int m0 = 0; m0 < NTOK; m0 += 64) {
        // stage K, V tiles + bias tile + col mask
        #pragma unroll
        for (int i = t; i < 64*32; i += 256) {
            int r = i >> 5, c = (i & 31) << 3;
            *(uint4*)&Ks[r*256 + c] = *(const uint4*)&kh[(size_t)(m0+r)*DIM + c];
            *(uint4*)&Vs[r*256 + c] = *(const uint4*)&vh[(size_t)(m0+r)*DIM + c];
        }
        if (t < 64) cmask[t] = mask_idx[m0 + t];
        #pragma unroll
        for (int i = t; i < 64*16; i += 256) {
            int r = i >> 4, c = (i & 15) << 2;
            const float4 sp = *(const float4*)&spatial[(size_t)(n0+r)*NTOK + m0 + c];
            const float4 eg = *(const float4*)&edge   [(size_t)(n0+r)*NTOK + m0 + c];
            float4 s4;
            s4.x = sp.x + eg.x; s4.y = sp.y + eg.y;
            s4.z = sp.z + eg.z; s4.w = sp.w + eg.w;
            *(float4*)&Sb[r*72 + c] = s4;
        }
        __syncthreads();

        // S = (q/16) K^T + (spatial+edge)  — bias preloaded as accumulator
        wmma::fragment<wmma::accumulator,16,16,16,float> sacc[2];
        #pragma unroll
        for (int j = 0; j < 2; j++)
            wmma::load_matrix_sync(sacc[j], &Sb[(wr*16)*72 + wc*32 + j*16], 72, wmma::mem_row_major);
        #pragma unroll
        for (int kk = 0; kk < 16; kk++) {
            wmma::fragment<wmma::matrix_a,16,16,16,__nv_bfloat16,wmma::row_major> af;
            wmma::load_matrix_sync(af, &Qs[(wr*16)*256 + kk*16], 256);
            #pragma unroll
            for (int j = 0; j < 2; j++) {
                wmma::fragment<wmma::matrix_b,16,16,16,__nv_bfloat16,wmma::col_major> bfr;
                wmma::load_matrix_sync(bfr, &Ks[(wc*32 + j*16)*256 + kk*16], 256);
                wmma::mma_sync(sacc[j], af, bfr, sacc[j]);
            }
        }
        __syncthreads();
        #pragma unroll
        for (int j = 0; j < 2; j++)
            wmma::store_matrix_sync(&Sb[(wr*16)*72 + wc*32 + j*16], sacc[j], 72, wmma::mem_row_major);
        __syncthreads();

        // masked exp (no max subtraction: logits are bounded, fp32 cannot overflow)
        {
            int rok = rmask[er];
            float lp = 0.f;
            #pragma unroll
            for (int j = 0; j < 16; j++) {
                int c = ec + j;
                float s = Sb[er*72 + c];
                float p = (rok && cmask[c]) ? __expf(s) : 0.f;
                lp += p;
                Ps[er*72 + c] = __float2bfloat16(p);
            }
            lsum += lp;
        }
        __syncthreads();

        // O += P @ V
        #pragma unroll
        for (int kk = 0; kk < 4; kk++) {
            wmma::fragment<wmma::matrix_a,16,16,16,__nv_bfloat16,wmma::row_major> af;
            wmma::load_matrix_sync(af, &Ps[(wr*16)*72 + kk*16], 72);
            #pragma unroll
            for (int j = 0; j < 8; j++) {
                wmma::fragment<wmma::matrix_b,16,16,16,__nv_bfloat16,wmma::row_major> bfr;
                wmma::load_matrix_sync(bfr, &Vs[(kk*16)*256 + wc*128 + j*16], 256);
                wmma::mma_sync(o[j], af, bfr, o[j]);
            }
        }
        __syncthreads();
    }

    // row-sum reduce (4 consecutive lanes per row), fully-masked rows -> 0
    lsum += __shfl_xor_sync(0xffffffffu, lsum, 1);
    lsum += __shfl_xor_sync(0xffffffffu, lsum, 2);
    if ((t & 3) == 0) linv[er] = (lsum > 0.f) ? (1.0f / lsum) : 0.0f;
    __syncthreads();

    #pragma unroll
    for (int j = 0; j < 8; j++)
        wmma::store_matrix_sync(&Os[(wr*16)*260 + wc*128 + j*16], o[j], 260, wmma::mem_row_major);
    __syncthreads();

    for (int i = t; i < 64*256; i += 256) {
        int r = i >> 8, c = i & 255;
        float vv = Os[r*260 + c] * linv[r];
        g_cat[(size_t)(n0+r)*(NHEAD*DIM) + h*DIM + c] = __float2bfloat16(vv);
    }
}

// ---------------- launch ----------------
#define GEMM_SMEM (128*132*4)

extern "C" void kernel_launch(void* const* d_in, const int* in_sizes, int n_in,
                              void* d_out, int out_size)
{
    (void)in_sizes; (void)n_in; (void)out_size;
    const float* x        = (const float*)d_in[0];
    const int*   mask_idx = (const int*)  d_in[1];
    const float* spatial  = (const float*)d_in[2];
    const float* edge     = (const float*)d_in[3];
    const float* ln1_g    = (const float*)d_in[4];
    const float* ln1_b    = (const float*)d_in[5];
    const float* Wq       = (const float*)d_in[6];
    const float* bq       = (const float*)d_in[7];
    const float* Wk       = (const float*)d_in[8];
    const float* bk       = (const float*)d_in[9];
    const float* Wv       = (const float*)d_in[10];
    const float* bv       = (const float*)d_in[11];
    const float* Wo       = (const float*)d_in[12];
    const float* bo       = (const float*)d_in[13];
    const float* ln2_g    = (const float*)d_in[14];
    const float* ln2_b    = (const float*)d_in[15];
    const float* Wff      = (const float*)d_in[16];
    const float* bff      = (const float*)d_in[17];
    float* out = (float*)d_out;

    cudaFuncSetAttribute((const void*)gemm_kernel<0>,
                         cudaFuncAttributeMaxDynamicSharedMemorySize, GEMM_SMEM);
    cudaFuncSetAttribute((const void*)gemm_kernel<1>,
                         cudaFuncAttributeMaxDynamicSharedMemorySize, GEMM_SMEM);
    cudaFuncSetAttribute((const void*)attn_kernel,
                         cudaFuncAttributeMaxDynamicSharedMemorySize, ATT_SMEM);

    __nv_bfloat16 *xln, *wqkv, *wo, *wff, *qkv, *cat, *xln2;
    float *xout;
    cudaGetSymbolAddress((void**)&xln,  g_xln);
    cudaGetSymbolAddress((void**)&wqkv, g_wqkv);
    cudaGetSymbolAddress((void**)&wo,   g_wo);
    cudaGetSymbolAddress((void**)&wff,  g_wff);
    cudaGetSymbolAddress((void**)&qkv,  g_qkv);
    cudaGetSymbolAddress((void**)&cat,  g_cat);
    cudaGetSymbolAddress((void**)&xout, g_xout);
    cudaGetSymbolAddress((void**)&xln2, g_xln2);

    // 1) LN1 -> bf16
    ln_kernel<<<NTOK, 256>>>(x, ln1_g, ln1_b, xln);

    // 2) weight conversions to bf16
    cvt_kernel<<<HDD/256, 256>>>(Wq, wqkv,          HDD);
    cvt_kernel<<<HDD/256, 256>>>(Wk, wqkv +   HDD,  HDD);
    cvt_kernel<<<HDD/256, 256>>>(Wv, wqkv + 2*HDD,  HDD);
    cvt_kernel<<<(DIM*NHEAD*DIM)/256, 256>>>(Wo,  wo,  DIM*NHEAD*DIM);
    cvt_kernel<<<(DIM*DIM)/256,       256>>>(Wff, wff, DIM*DIM);

    // 3) fused QKV projection: [4096,256] @ [6144,256]^T
    gemm_kernel<0><<<dim3(32,48), 256, GEMM_SMEM>>>(xln, wqkv, DIM,
                                                    bq, bk, bv, nullptr, nullptr, qkv);

    // 4) attention (h fastest in grid => spatial/edge L2 reuse across heads)
    attn_kernel<<<dim3(NHEAD, NTOK/64), 256, ATT_SMEM>>>(spatial, edge, mask_idx);

    // 5) output projection + residual: x_out = cat @ Wo^T + bo + x
    gemm_kernel<1><<<dim3(32,2), 256, GEMM_SMEM>>>(cat, wo, NHEAD*DIM,
                                                   bo, nullptr, nullptr, x, xout, nullptr);

    // 6) LN2 -> bf16
    ln_kernel<<<NTOK, 256>>>(xout, ln2_g, ln2_b, xln2);

    // 7) FF + residual: out = ln2 @ Wff^T + bff + x_out
    gemm_kernel<1><<<dim3(32,2), 256, GEMM_SMEM>>>(xln2, wff, DIM,
                                                   bff, nullptr, nullptr, xout, out, nullptr);
}

// round 2
// speedup vs baseline: 2.5577x; 2.5577x over previous
#include <cuda_runtime.h>
#include <cuda_bf16.h>
#include <mma.h>

using namespace nvcuda;

#define NTOK 4096
#define DIM 256
#define NHEAD 8
#define HDD (NHEAD*DIM*DIM)

// ---------------- scratch (device globals; no cudaMalloc allowed) ----------------
__device__ __nv_bfloat16 g_xln [NTOK*DIM];      // compacted valid rows
__device__ __nv_bfloat16 g_wqkv[3*HDD];
__device__ __nv_bfloat16 g_wo  [DIM*NHEAD*DIM];
__device__ __nv_bfloat16 g_wff [DIM*DIM];
__device__ __nv_bfloat16 g_qkv [3ULL*NHEAD*NTOK*DIM];   // compacted rows per head
__device__ __nv_bfloat16 g_cat [(size_t)NTOK*NHEAD*DIM]; // full domain (pre-zeroed)
__device__ float         g_xout[NTOK*DIM];
__device__ __nv_bfloat16 g_xln2[NTOK*DIM];
__device__ int           g_nvalid;
__device__ int           g_idx [NTOK];          // compacted -> original token id
__device__ int           g_cidx[NTOK];          // original -> compacted (or -1)

// ---------------- mask compaction: prefix scan over 4096 mask values -------------
__global__ void compact_kernel(const int* __restrict__ mask)
{
    __shared__ int warpsum[32];
    int t = threadIdx.x;              // 1024 threads, 4 elems each
    int base = t * 4;
    int m[4], s = 0;
    #pragma unroll
    for (int i = 0; i < 4; i++) { m[i] = (mask[base+i] != 0); s += m[i]; }
    int lane = t & 31, w = t >> 5;
    int pre = s;
    #pragma unroll
    for (int o = 1; o < 32; o <<= 1) {
        int v = __shfl_up_sync(0xffffffffu, pre, o);
        if (lane >= o) pre += v;
    }
    if (lane == 31) warpsum[w] = pre;
    __syncthreads();
    if (t < 32) {
        int v = warpsum[t];
        #pragma unroll
        for (int o = 1; o < 32; o <<= 1) {
            int u = __shfl_up_sync(0xffffffffu, v, o);
            if (t >= o) v += u;
        }
        warpsum[t] = v;
    }
    __syncthreads();
    int off = pre - s + ((w > 0) ? warpsum[w-1] : 0);
    #pragma unroll
    for (int i = 0; i < 4; i++) {
        if (m[i]) { g_idx[off] = base + i; g_cidx[base+i] = off; off++; }
        else      { g_cidx[base+i] = -1; }
    }
    if (t == 0) g_nvalid = warpsum[31];
}

// ---------------- layernorm: fp32 in -> bf16 out (optionally compacted) ----------
template<int COMPACT>
__global__ void ln_kernel(const float* __restrict__ x, const float* __restrict__ g,
                          const float* __restrict__ b, __nv_bfloat16* __restrict__ out)
{
    int row = blockIdx.x;
    int orow = row;
    if (COMPACT) { orow = g_cidx[row]; if (orow < 0) return; }
    int t = threadIdx.x;
    float v = x[row*DIM + t];
    float sum = v, sq = v*v;
    #pragma unroll
    for (int o = 16; o > 0; o >>= 1) {
        sum += __shfl_xor_sync(0xffffffffu, sum, o);
        sq  += __shfl_xor_sync(0xffffffffu, sq,  o);
    }
    __shared__ float s1[8], s2[8];
    if ((t & 31) == 0) { s1[t>>5] = sum; s2[t>>5] = sq; }
    __syncthreads();
    __shared__ float smu, srstd;
    if (t == 0) {
        float S = 0.f, Q = 0.f;
        #pragma unroll
        for (int i = 0; i < 8; i++) { S += s1[i]; Q += s2[i]; }
        float m = S * (1.0f/DIM);
        smu = m;
        srstd = rsqrtf(Q * (1.0f/DIM) - m*m + 1e-5f);
    }
    __syncthreads();
    out[orow*DIM + t] = __float2bfloat16((v - smu) * srstd * g[t] + b[t]);
}

// ---------------- fp32 -> bf16 weight conversion ----------------
__global__ void cvt_kernel(const float* __restrict__ src, __nv_bfloat16* __restrict__ dst, int n)
{
    int i = blockIdx.x * blockDim.x + threadIdx.x;
    if (i < n) dst[i] = __float2bfloat16(src[i]);
}

// ---------------- zero g_cat ----------------
__global__ void zero_cat_kernel()
{
    size_t i = (size_t)(blockIdx.x * blockDim.x + threadIdx.x) * 8;
    *(uint4*)&g_cat[i] = make_uint4(0,0,0,0);
}

// ---------------- generic 128x128 bf16 WMMA GEMM: C = A @ B^T (+epilogue) -------
// EPI 0 (+COMPACT): QKV scatter (bias + q-scale, bf16 out); EPI 1: bias+residual f32
template<int EPI, int COMPACT>
__global__ void gemm_kernel(const __nv_bfloat16* __restrict__ A,
                            const __nv_bfloat16* __restrict__ B,
                            int K,
                            const float* __restrict__ b0,
                            const float* __restrict__ b1,
                            const float* __restrict__ b2,
                            const float* __restrict__ res,
                            float* __restrict__ outf,
                            __nv_bfloat16* __restrict__ outb)
{
    int bm = blockIdx.x * 128;
    if (COMPACT && bm >= g_nvalid) return;

    extern __shared__ char smem[];
    __nv_bfloat16* As = (__nv_bfloat16*)smem;          // [128][16]
    __nv_bfloat16* Bs = As + 128*16;                   // [128][16]
    float* Cs = (float*)smem;                          // [128][132] (aliases As/Bs)

    int bn = blockIdx.y * 128;
    int t = threadIdx.x;
    int w = t >> 5;
    int wr = w & 3, wc = w >> 2;   // 4x2 warp grid, each warp 32x64

    wmma::fragment<wmma::accumulator,16,16,16,float> acc[2][4];
    #pragma unroll
    for (int i = 0; i < 2; i++)
        #pragma unroll
        for (int j = 0; j < 4; j++)
            wmma::fill_fragment(acc[i][j], 0.0f);

    int lr = t >> 1;
    int lc = (t & 1) << 3;

    for (int k0 = 0; k0 < K; k0 += 16) {
        *(uint4*)&As[lr*16 + lc] = *(const uint4*)&A[(size_t)(bm+lr)*K + k0 + lc];
        *(uint4*)&Bs[lr*16 + lc] = *(const uint4*)&B[(size_t)(bn+lr)*K + k0 + lc];
        __syncthreads();
        wmma::fragment<wmma::matrix_a,16,16,16,__nv_bfloat16,wmma::row_major> af[2];
        #pragma unroll
        for (int i = 0; i < 2; i++)
            wmma::load_matrix_sync(af[i], As + (wr*32 + i*16)*16, 16);
        #pragma unroll
        for (int j = 0; j < 4; j++) {
            wmma::fragment<wmma::matrix_b,16,16,16,__nv_bfloat16,wmma::col_major> bfr;
            wmma::load_matrix_sync(bfr, Bs + (wc*64 + j*16)*16, 16);
            #pragma unroll
            for (int i = 0; i < 2; i++)
                wmma::mma_sync(acc[i][j], af[i], bfr, acc[i][j]);
        }
        __syncthreads();
    }

    #pragma unroll
    for (int i = 0; i < 2; i++)
        #pragma unroll
        for (int j = 0; j < 4; j++)
            wmma::store_matrix_sync(&Cs[(wr*32 + i*16)*132 + wc*64 + j*16], acc[i][j],
                                    132, wmma::mem_row_major);
    __syncthreads();

    for (int idx = t; idx < 128*128; idx += 256) {
        int r = idx >> 7, c = idx & 127;
        int n = bm + r, cc = bn + c;
        float v = Cs[r*132 + c];
        if (EPI == 0) {
            int which = cc >> 11;               // 0=q, 1=k, 2=v
            const float* bp = (which == 0) ? b0 : (which == 1) ? b1 : b2;
            v += bp[cc & 2047];
            if (which == 0) v *= 0.0625f;       // 1/sqrt(D), D=256
            int h = (cc >> 8) & 7;
            int e = cc & 255;
            outb[((size_t)which*NHEAD + h)*NTOK*DIM + (size_t)n*DIM + e] = __float2bfloat16(v);
        } else {
            v += b0[cc] + res[(size_t)n*DIM + cc];
            outf[(size_t)n*DIM + cc] = v;
        }
    }
}

// ---------------- fused biased attention over COMPACTED tokens -------------------
// grid: (NHEAD, NTOK/64). Each block: 64 compacted query rows of one head.
// smem: Qs 32K | Ks 32K | Vs 32K | Sb (64x72 f32) | Ps (64x72 bf16)
#define ATT_SMEM (64*256*2*3 + 64*72*4 + 64*72*2)

__global__ void attn_kernel(const float* __restrict__ spatial,
                            const float* __restrict__ edge)
{
    int Nv = g_nvalid;
    int n0 = blockIdx.y * 64;
    if (n0 >= Nv) return;

    extern __shared__ char smem[];
    __nv_bfloat16* Qs = (__nv_bfloat16*)smem;
    __nv_bfloat16* Ks = Qs + 64*256;
    __nv_bfloat16* Vs = Ks + 64*256;
    float*         Sb = (float*)(Vs + 64*256);           // [64][72]
    __nv_bfloat16* Ps = (__nv_bfloat16*)(Sb + 64*72);    // [64][72]
    float*         Os = (float*)Ks;                      // epilogue alias [64][260]

    __shared__ float linv[64];
    __shared__ int   rg[64];                             // global token ids (rows)

    int h  = blockIdx.x;
    int t  = threadIdx.x;
    int w  = t >> 5;
    int wr = w & 3, wc = w >> 2;

    const __nv_bfloat16* qh = g_qkv + (size_t)h*NTOK*DIM;
    const __nv_bfloat16* kh = g_qkv + (size_t)(NHEAD   + h)*NTOK*DIM;
    const __nv_bfloat16* vh = g_qkv + (size_t)(2*NHEAD + h)*NTOK*DIM;

    #pragma unroll
    for (int i = t; i < 64*32; i += 256) {
        int r = i >> 5, c = (i & 31) << 3;
        *(uint4*)&Qs[r*256 + c] = *(const uint4*)&qh[(size_t)(n0+r)*DIM + c];
    }
    if (t < 64) rg[t] = g_idx[n0 + t];

    wmma::fragment<wmma::accumulator,16,16,16,float> o[8];
    #pragma unroll
    for (int j = 0; j < 8; j++) wmma::fill_fragment(o[j], 0.0f);

    float lsum = 0.f;
    int er = t >> 2;            // exp row (4 threads/row)
    int ec = (t & 3) << 4;      // 16 cols per thread
    int mend = (Nv + 63) & ~63;

    #pragma unroll 1
    for (int m0 = 0; m0 < mend; m0 += 64) {
        // stage K, V tiles (compacted rows: contiguous, no gather)
        #pragma unroll
        for (int i = t; i < 64*32; i += 256) {
            int r = i >> 5, c = (i & 31) << 3;
            *(uint4*)&Ks[r*256 + c] = *(const uint4*)&kh[(size_t)(m0+r)*DIM + c];
            *(uint4*)&Vs[r*256 + c] = *(const uint4*)&vh[(size_t)(m0+r)*DIM + c];
        }
        // bias tile: gathered via idx (rows from smem-staged rg, cols via __ldg idx)
        #pragma unroll
        for (int i = t; i < 64*64; i += 256) {
            int r = i >> 6, c = i & 63;
            int gi = rg[r];
            int gj = __ldg(&g_idx[m0 + c]);
            size_t off = (size_t)gi*NTOK + gj;
            Sb[r*72 + c] = __ldg(&spatial[off]) + __ldg(&edge[off]);
        }
        __syncthreads();

        // S = (q/16) K^T + (spatial+edge) — bias preloaded as accumulator
        wmma::fragment<wmma::accumulator,16,16,16,float> sacc[2];
        #pragma unroll
        for (int j = 0; j < 2; j++)
            wmma::load_matrix_sync(sacc[j], &Sb[(wr*16)*72 + wc*32 + j*16], 72, wmma::mem_row_major);
        #pragma unroll
        for (int kk = 0; kk < 16; kk++) {
            wmma::fragment<wmma::matrix_a,16,16,16,__nv_bfloat16,wmma::row_major> af;
            wmma::load_matrix_sync(af, &Qs[(wr*16)*256 + kk*16], 256);
            #pragma unroll
            for (int j = 0; j < 2; j++) {
                wmma::fragment<wmma::matrix_b,16,16,16,__nv_bfloat16,wmma::col_major> bfr;
                wmma::load_matrix_sync(bfr, &Ks[(wc*32 + j*16)*256 + kk*16], 256);
                wmma::mma_sync(sacc[j], af, bfr, sacc[j]);
            }
        }
        __syncthreads();
        #pragma unroll
        for (int j = 0; j < 2; j++)
            wmma::store_matrix_sync(&Sb[(wr*16)*72 + wc*32 + j*16], sacc[j], 72, wmma::mem_row_major);
        __syncthreads();

        // exp (no max subtraction: logits bounded). Zero padded rows/cols.
        {
            bool rok = (n0 + er) < Nv;
            float lp = 0.f;
            #pragma unroll
            for (int j = 0; j < 16; j++) {
                int c = ec + j;
                float s = Sb[er*72 + c];
                float p = (rok && (m0 + c) < Nv) ? __expf(s) : 0.f;
                lp += p;
                Ps[er*72 + c] = __float2bfloat16(p);
            }
            lsum += lp;
        }
        __syncthreads();

        // O += P @ V
        #pragma unroll
        for (int kk = 0; kk < 4; kk++) {
            wmma::fragment<wmma::matrix_a,16,16,16,__nv_bfloat16,wmma::row_major> af;
            wmma::load_matrix_sync(af, &Ps[(wr*16)*72 + kk*16], 72);
            #pragma unroll
            for (int j = 0; j < 8; j++) {
                wmma::fragment<wmma::matrix_b,16,16,16,__nv_bfloat16,wmma::row_major> bfr;
                wmma::load_matrix_sync(bfr, &Vs[(kk*16)*256 + wc*128 + j*16], 256);
                wmma::mma_sync(o[j], af, bfr, o[j]);
            }
        }
        __syncthreads();
    }

    // row-sum reduce (4 consecutive lanes per row)
    lsum += __shfl_xor_sync(0xffffffffu, lsum, 1);
    lsum += __shfl_xor_sync(0xffffffffu, lsum, 2);
    if ((t & 3) == 0) linv[er] = (lsum > 0.f) ? (1.0f / lsum) : 0.0f;
    __syncthreads();

    #pragma unroll
    for (int j = 0; j < 8; j++)
        wmma::store_matrix_sync(&Os[(wr*16)*260 + wc*128 + j*16], o[j], 260, wmma::mem_row_major);
    __syncthreads();

    for (int i = t; i < 64*256; i += 256) {
        int r = i >> 8, c = i & 255;
        if (n0 + r < Nv) {
            float vv = Os[r*260 + c] * linv[r];
            g_cat[(size_t)rg[r]*(NHEAD*DIM) + h*DIM + c] = __float2bfloat16(vv);
        }
    }
}

// ---------------- launch ----------------
#define GEMM_SMEM (128*132*4)

extern "C" void kernel_launch(void* const* d_in, const int* in_sizes, int n_in,
                              void* d_out, int out_size)
{
    (void)in_sizes; (void)n_in; (void)out_size;
    const float* x        = (const float*)d_in[0];
    const int*   mask_idx = (const int*)  d_in[1];
    const float* spatial  = (const float*)d_in[2];
    const float* edge     = (const float*)d_in[3];
    const float* ln1_g    = (const float*)d_in[4];
    const float* ln1_b    = (const float*)d_in[5];
    const float* Wq       = (const float*)d_in[6];
    const float* bq       = (const float*)d_in[7];
    const float* Wk       = (const float*)d_in[8];
    const float* bk       = (const float*)d_in[9];
    const float* Wv       = (const float*)d_in[10];
    const float* bv       = (const float*)d_in[11];
    const float* Wo       = (const float*)d_in[12];
    const float* bo       = (const float*)d_in[13];
    const float* ln2_g    = (const float*)d_in[14];
    const float* ln2_b    = (const float*)d_in[15];
    const float* Wff      = (const float*)d_in[16];
    const float* bff      = (const float*)d_in[17];
    float* out = (float*)d_out;

    cudaFuncSetAttribute((const void*)gemm_kernel<0,1>,
                         cudaFuncAttributeMaxDynamicSharedMemorySize, GEMM_SMEM);
    cudaFuncSetAttribute((const void*)gemm_kernel<1,0>,
                         cudaFuncAttributeMaxDynamicSharedMemorySize, GEMM_SMEM);
    cudaFuncSetAttribute((const void*)attn_kernel,
                         cudaFuncAttributeMaxDynamicSharedMemorySize, ATT_SMEM);

    __nv_bfloat16 *xln, *wqkv, *wo, *wff, *qkv, *cat, *xln2;
    float *xout;
    cudaGetSymbolAddress((void**)&xln,  g_xln);
    cudaGetSymbolAddress((void**)&wqkv, g_wqkv);
    cudaGetSymbolAddress((void**)&wo,   g_wo);
    cudaGetSymbolAddress((void**)&wff,  g_wff);
    cudaGetSymbolAddress((void**)&qkv,  g_qkv);
    cudaGetSymbolAddress((void**)&cat,  g_cat);
    cudaGetSymbolAddress((void**)&xout, g_xout);
    cudaGetSymbolAddress((void**)&xln2, g_xln2);

    // 0) mask compaction
    compact_kernel<<<1, 1024>>>(mask_idx);

    // 1) LN1 -> bf16, compacted valid rows only
    ln_kernel<1><<<NTOK, 256>>>(x, ln1_g, ln1_b, xln);

    // 2) weight conversions to bf16
    cvt_kernel<<<HDD/256, 256>>>(Wq, wqkv,          HDD);
    cvt_kernel<<<HDD/256, 256>>>(Wk, wqkv +   HDD,  HDD);
    cvt_kernel<<<HDD/256, 256>>>(Wv, wqkv + 2*HDD,  HDD);
    cvt_kernel<<<(DIM*NHEAD*DIM)/256, 256>>>(Wo,  wo,  DIM*NHEAD*DIM);
    cvt_kernel<<<(DIM*DIM)/256,       256>>>(Wff, wff, DIM*DIM);

    // 3) fused QKV projection on compacted rows (blocks beyond Nv exit)
    gemm_kernel<0,1><<<dim3(32,48), 256, GEMM_SMEM>>>(xln, wqkv, DIM,
                                                      bq, bk, bv, nullptr, nullptr, qkv);

    // 4) zero cat (masked rows must be exactly 0), then compacted attention
    zero_cat_kernel<<<(NTOK*NHEAD*DIM/8)/256, 256>>>();
    attn_kernel<<<dim3(NHEAD, NTOK/64), 256, ATT_SMEM>>>(spatial, edge);

    // 5) output projection + residual: x_out = cat @ Wo^T + bo + x
    gemm_kernel<1,0><<<dim3(32,2), 256, GEMM_SMEM>>>(cat, wo, NHEAD*DIM,
                                                     bo, nullptr, nullptr, x, xout, nullptr);

    // 6) LN2 -> bf16 (full domain)
    ln_kernel<0><<<NTOK, 256>>>(xout, ln2_g, ln2_b, xln2);

    // 7) FF + residual: out = ln2 @ Wff^T + bff + x_out
    gemm_kernel<1,0><<<dim3(32,2), 256, GEMM_SMEM>>>(xln2, wff, DIM,
                                                     bff, nullptr, nullptr, xout, out, nullptr);
}

// round 3
// speedup vs baseline: 8.8952x; 3.4778x over previous
#include <cuda_runtime.h>
#include <cuda_bf16.h>
#include <mma.h>
#include <cstdint>

using namespace nvcuda;

#define NTOK 4096
#define DIM 256
#define NHEAD 8
#define HDD (NHEAD*DIM*DIM)
#define BSTRIDE 4128            // padded fp32 row stride of compact bias

// ---------------- scratch (device globals; no cudaMalloc allowed) ----------------
__device__ __nv_bfloat16 g_xln [NTOK*DIM];      // compacted valid rows
__device__ __nv_bfloat16 g_wqkv[3*HDD];
__device__ __nv_bfloat16 g_wo  [DIM*NHEAD*DIM];
__device__ __nv_bfloat16 g_wff [DIM*DIM];
__device__ __nv_bfloat16 g_qkv [3ULL*NHEAD*NTOK*DIM];    // compacted rows per head
__device__ __nv_bfloat16 g_cat [(size_t)NTOK*NHEAD*DIM]; // valid rows written; masked zfilled at Wo load
__device__ float         g_xout[NTOK*DIM];
__device__ __nv_bfloat16 g_xln2[NTOK*DIM];
__device__ float         g_bias[(size_t)NTOK*BSTRIDE];   // compact (spatial+edge)
__device__ int           g_nvalid;
__device__ int           g_idx [NTOK];          // compacted -> original token id
__device__ int           g_cidx[NTOK];          // original -> compacted (or -1)

// ---------------- cp.async helpers ----------------
__device__ __forceinline__ void cp16(void* dst, const void* src) {
    uint32_t d = (uint32_t)__cvta_generic_to_shared(dst);
    asm volatile("cp.async.cg.shared.global [%0], [%1], 16;\n" :: "r"(d), "l"(src));
}
__device__ __forceinline__ void cp16p(void* dst, const void* src, bool p) {
    uint32_t d = (uint32_t)__cvta_generic_to_shared(dst);
    int sz = p ? 16 : 0;
    asm volatile("cp.async.cg.shared.global [%0], [%1], 16, %2;\n" :: "r"(d), "l"(src), "r"(sz));
}
__device__ __forceinline__ void cp_commit() {
    asm volatile("cp.async.commit_group;\n");
}
__device__ __forceinline__ void cp_wait0() {
    asm volatile("cp.async.wait_group 0;\n");
}

// ---------------- mask compaction: prefix scan over 4096 mask values -------------
__global__ void compact_kernel(const int* __restrict__ mask)
{
    __shared__ int warpsum[32];
    int t = threadIdx.x;              // 1024 threads, 4 elems each
    int base = t * 4;
    int m[4], s = 0;
    #pragma unroll
    for (int i = 0; i < 4; i++) { m[i] = (mask[base+i] != 0); s += m[i]; }
    int lane = t & 31, w = t >> 5;
    int pre = s;
    #pragma unroll
    for (int o = 1; o < 32; o <<= 1) {
        int v = __shfl_up_sync(0xffffffffu, pre, o);
        if (lane >= o) pre += v;
    }
    if (lane == 31) warpsum[w] = pre;
    __syncthreads();
    if (t < 32) {
        int v = warpsum[t];
        #pragma unroll
        for (int o = 1; o < 32; o <<= 1) {
            int u = __shfl_up_sync(0xffffffffu, v, o);
            if (t >= o) v += u;
        }
        warpsum[t] = v;
    }
    __syncthreads();
    int off = pre - s + ((w > 0) ? warpsum[w-1] : 0);
    #pragma unroll
    for (int i = 0; i < 4; i++) {
        if (m[i]) { g_idx[off] = base + i; g_cidx[base+i] = off; off++; }
        else      { g_cidx[base+i] = -1; }
    }
    if (t == 0) g_nvalid = warpsum[31];
}

// ---------------- fused weight conversion fp32 -> bf16 ----------------
__global__ void cvt_all_kernel(const float* __restrict__ Wq, const float* __restrict__ Wk,
                               const float* __restrict__ Wv, const float* __restrict__ Wo,
                               const float* __restrict__ Wff)
{
    int i = blockIdx.x * 256 + threadIdx.x;
    if      (i <   HDD) g_wqkv[i] = __float2bfloat16(Wq[i]);
    else if (i < 2*HDD) g_wqkv[i] = __float2bfloat16(Wk[i -   HDD]);
    else if (i < 3*HDD) g_wqkv[i] = __float2bfloat16(Wv[i - 2*HDD]);
    else if (i < 4*HDD) g_wo [i - 3*HDD] = __float2bfloat16(Wo [i - 3*HDD]);
    else                g_wff[i - 4*HDD] = __float2bfloat16(Wff[i - 4*HDD]);
}

// ---------------- layernorm: fp32 in -> bf16 out (optionally compacted) ----------
template<int COMPACT>
__global__ void ln_kernel(const float* __restrict__ x, const float* __restrict__ g,
                          const float* __restrict__ b, __nv_bfloat16* __restrict__ out)
{
    int row = blockIdx.x;
    int orow = row;
    if (COMPACT) { orow = g_cidx[row]; if (orow < 0) return; }
    int t = threadIdx.x;
    float v = x[row*DIM + t];
    float sum = v, sq = v*v;
    #pragma unroll
    for (int o = 16; o > 0; o >>= 1) {
        sum += __shfl_xor_sync(0xffffffffu, sum, o);
        sq  += __shfl_xor_sync(0xffffffffu, sq,  o);
    }
    __shared__ float s1[8], s2[8];
    if ((t & 31) == 0) { s1[t>>5] = sum; s2[t>>5] = sq; }
    __syncthreads();
    __shared__ float smu, srstd;
    if (t == 0) {
        float S = 0.f, Q = 0.f;
        #pragma unroll
        for (int i = 0; i < 8; i++) { S += s1[i]; Q += s2[i]; }
        float m = S * (1.0f/DIM);
        smu = m;
        srstd = rsqrtf(Q * (1.0f/DIM) - m*m + 1e-5f);
    }
    __syncthreads();
    out[orow*DIM + t] = __float2bfloat16((v - smu) * srstd * g[t] + b[t]);
}

// ---------------- compact bias precompute: g_bias[i,j] = sp[gi,gj]+ed[gi,gj] -----
__global__ void bias_pre_kernel(const float* __restrict__ spatial,
                                const float* __restrict__ edge)
{
    int i = blockIdx.y;
    if (i >= g_nvalid) return;
    int j = blockIdx.x * 256 + threadIdx.x;
    if (j >= g_nvalid) return;
    int gi = g_idx[i];
    int gj = __ldg(&g_idx[j]);
    size_t off = (size_t)gi*NTOK + gj;
    g_bias[(size_t)i*BSTRIDE + j] = __ldg(&spatial[off]) + __ldg(&edge[off]);
}

// ---------------- 128x128 bf16 WMMA GEMM, 64-wide K panels, cp.async 2-stage -----
// C = A @ B^T.  EPI 0 (+COMPACT): QKV scatter (bias + q-scale, bf16 out)
//               EPI 1: bias + residual, fp32 out.  ZMASK: zero-fill masked A rows.
#define GEMM_SMEM (4*128*72*2 > 128*132*4 ? 4*128*72*2 : 128*132*4)   // 73728

template<int EPI, int COMPACT, int ZMASK>
__global__ void gemm_kernel(const __nv_bfloat16* __restrict__ A,
                            const __nv_bfloat16* __restrict__ B,
                            int K,
                            const float* __restrict__ b0,
                            const float* __restrict__ b1,
                            const float* __restrict__ b2,
                            const float* __restrict__ res,
                            float* __restrict__ outf,
                            __nv_bfloat16* __restrict__ outb)
{
    int bm = blockIdx.x * 128;
    if (COMPACT && bm >= g_nvalid) return;

    extern __shared__ char smem[];
    __nv_bfloat16* As = (__nv_bfloat16*)smem;          // 2 stages [128][72]
    __nv_bfloat16* Bs = As + 2*128*72;                 // 2 stages [128][72]
    float* Cs = (float*)smem;                          // [128][132] alias

    int bn = blockIdx.y * 128;
    int t = threadIdx.x;
    int w = t >> 5;
    int wr = w & 3, wc = w >> 2;   // 4x2 warp grid, each warp 32x64

    // per-thread chunk rows (constant over panels): id = t + k*256, row=id>>3
    bool pm[4];
    #pragma unroll
    for (int k = 0; k < 4; k++) {
        int r = (t + k*256) >> 3;
        pm[k] = !ZMASK || (g_cidx[bm + r] >= 0);
    }

    wmma::fragment<wmma::accumulator,16,16,16,float> acc[2][4];
    #pragma unroll
    for (int i = 0; i < 2; i++)
        #pragma unroll
        for (int j = 0; j < 4; j++)
            wmma::fill_fragment(acc[i][j], 0.0f);

    int nP = K >> 6;

    auto prefetch = [&](int p, int st) {
        const __nv_bfloat16* Ap = A + (size_t)bm*K + p*64;
        const __nv_bfloat16* Bp = B + (size_t)bn*K + p*64;
        __nv_bfloat16* Ad = As + st*128*72;
        __nv_bfloat16* Bd = Bs + st*128*72;
        #pragma unroll
        for (int k = 0; k < 4; k++) {
            int id = t + k*256;
            int r = id >> 3, c = (id & 7) << 3;
            cp16p(Ad + r*72 + c, Ap + (size_t)r*K + c, pm[k]);
            cp16 (Bd + r*72 + c, Bp + (size_t)r*K + c);
        }
        cp_commit();
    };

    prefetch(0, 0);
    for (int p = 0; p < nP; p++) {
        cp_wait0();
        __syncthreads();
        if (p + 1 < nP) prefetch(p + 1, (p + 1) & 1);
        int st = p & 1;
        __nv_bfloat16* Ad = As + st*128*72;
        __nv_bfloat16* Bd = Bs + st*128*72;
        #pragma unroll
        for (int kk = 0; kk < 4; kk++) {
            wmma::fragment<wmma::matrix_a,16,16,16,__nv_bfloat16,wmma::row_major> af[2];
            #pragma unroll
            for (int i = 0; i < 2; i++)
                wmma::load_matrix_sync(af[i], Ad + (wr*32 + i*16)*72 + kk*16, 72);
            #pragma unroll
            for (int j = 0; j < 4; j++) {
                wmma::fragment<wmma::matrix_b,16,16,16,__nv_bfloat16,wmma::col_major> bfr;
                wmma::load_matrix_sync(bfr, Bd + (wc*64 + j*16)*72 + kk*16, 72);
                #pragma unroll
                for (int i = 0; i < 2; i++)
                    wmma::mma_sync(acc[i][j], af[i], bfr, acc[i][j]);
            }
        }
        __syncthreads();
    }

    #pragma unroll
    for (int i = 0; i < 2; i++)
        #pragma unroll
        for (int j = 0; j < 4; j++)
            wmma::store_matrix_sync(&Cs[(wr*32 + i*16)*132 + wc*64 + j*16], acc[i][j],
                                    132, wmma::mem_row_major);
    __syncthreads();

    for (int idx = t; idx < 128*128; idx += 256) {
        int r = idx >> 7, c = idx & 127;
        int n = bm + r, cc = bn + c;
        float v = Cs[r*132 + c];
        if (EPI == 0) {
            int which = cc >> 11;               // 0=q, 1=k, 2=v
            const float* bp = (which == 0) ? b0 : (which == 1) ? b1 : b2;
            v += bp[cc & 2047];
            if (which == 0) v *= 0.0625f;       // 1/sqrt(D), D=256
            int h = (cc >> 8) & 7;
            int e = cc & 255;
            outb[((size_t)which*NHEAD + h)*NTOK*DIM + (size_t)n*DIM + e] = __float2bfloat16(v);
        } else {
            v += b0[cc] + res[(size_t)n*DIM + cc];
            outf[(size_t)n*DIM + cc] = v;
        }
    }
}

// ---------------- fused biased attention, compacted, cp.async 2-stage pipeline ---
// grid: (NHEAD, NTOK/64). Each block: 64 compacted query rows of one head.
// dyn smem layout (bytes):
//  Qs [64][264] bf16     @ 0       33792
//  Ks 2x[64][264] bf16   @ 33792   67584   (epilogue alias: Os [64][260] f32)
//  Vs 2x[64][264] bf16   @ 101376  67584
//  Bs 2x[64][68]  f32    @ 168960  34816
//  Sb [64][72]    f32    @ 203776  18432
//  Ps [64][72]    bf16   @ 222208   9216
//  rg [64] int           @ 231424    256
//  linv [64] f32         @ 231680    256      total 231936
#define ATT_SMEM 231936
#define QS 264

__global__ void attn_kernel()
{
    int Nv = g_nvalid;
    int n0 = blockIdx.y * 64;
    if (n0 >= Nv) return;

    extern __shared__ char smem[];
    __nv_bfloat16* Qs = (__nv_bfloat16*)smem;
    __nv_bfloat16* Ks = (__nv_bfloat16*)(smem + 33792);
    __nv_bfloat16* Vs = (__nv_bfloat16*)(smem + 101376);
    float*         Bs = (float*)        (smem + 168960);
    float*         Sb = (float*)        (smem + 203776);
    __nv_bfloat16* Ps = (__nv_bfloat16*)(smem + 222208);
    int*           rg = (int*)          (smem + 231424);
    float*         linv = (float*)      (smem + 231680);
    float*         Os = (float*)Ks;                      // epilogue alias [64][260]

    int h  = blockIdx.x;
    int t  = threadIdx.x;
    int w  = t >> 5;
    int wr = w & 3, wc = w >> 2;

    const __nv_bfloat16* qh = g_qkv + (size_t)h*NTOK*DIM;
    const __nv_bfloat16* kh = g_qkv + (size_t)(NHEAD   + h)*NTOK*DIM;
    const __nv_bfloat16* vh = g_qkv + (size_t)(2*NHEAD + h)*NTOK*DIM;

    int mend = (Nv + 63) & ~63;
    int T = mend >> 6;

    auto prefetch = [&](int m, int st) {
        int m0 = m << 6;
        __nv_bfloat16* Kd = Ks + st*64*QS;
        __nv_bfloat16* Vd = Vs + st*64*QS;
        float*         Bd = Bs + st*64*68;
        #pragma unroll
        for (int k = 0; k < 8; k++) {
            int id = t + k*256;
            int r = id >> 5, c = (id & 31) << 3;
            cp16(Kd + r*QS + c, kh + (size_t)(m0+r)*DIM + c);
            cp16(Vd + r*QS + c, vh + (size_t)(m0+r)*DIM + c);
        }
        #pragma unroll
        for (int k = 0; k < 4; k++) {
            int id = t + k*256;
            int r = id >> 4, c = (id & 15) << 2;
            cp16(Bd + r*68 + c, g_bias + (size_t)(n0+r)*BSTRIDE + m0 + c);
        }
        cp_commit();
    };

    // Q + first tile prefetch (one group)
    #pragma unroll
    for (int k = 0; k < 8; k++) {
        int id = t + k*256;
        int r = id >> 5, c = (id & 31) << 3;
        cp16(Qs + r*QS + c, qh + (size_t)(n0+r)*DIM + c);
    }
    if (t < 64) rg[t] = g_idx[n0 + t];
    prefetch(0, 0);

    wmma::fragment<wmma::accumulator,16,16,16,float> o[8];
    #pragma unroll
    for (int j = 0; j < 8; j++) wmma::fill_fragment(o[j], 0.0f);

    float lsum = 0.f;
    int er = t >> 2;            // exp row (4 threads/row)
    int ec = (t & 3) << 4;      // 16 cols per thread
    bool rok = (n0 + er) < Nv;

    #pragma unroll 1
    for (int m = 0; m < T; m++) {
        cp_wait0();
        __syncthreads();                        // stage m ready; all done with m-1
        if (m + 1 < T) prefetch(m + 1, (m + 1) & 1);
        int st = m & 1;
        int m0 = m << 6;
        __nv_bfloat16* Kd = Ks + st*64*QS;
        __nv_bfloat16* Vd = Vs + st*64*QS;
        float*         Bd = Bs + st*64*68;

        // S = (q/16) K^T + bias (bias preloaded as accumulator)
        wmma::fragment<wmma::accumulator,16,16,16,float> sacc[2];
        #pragma unroll
        for (int j = 0; j < 2; j++)
            wmma::load_matrix_sync(sacc[j], Bd + (wr*16)*68 + wc*32 + j*16, 68, wmma::mem_row_major);
        #pragma unroll
        for (int kk = 0; kk < 16; kk++) {
            wmma::fragment<wmma::matrix_a,16,16,16,__nv_bfloat16,wmma::row_major> af;
            wmma::load_matrix_sync(af, Qs + (wr*16)*QS + kk*16, QS);
            #pragma unroll
            for (int j = 0; j < 2; j++) {
                wmma::fragment<wmma::matrix_b,16,16,16,__nv_bfloat16,wmma::col_major> bfr;
                wmma::load_matrix_sync(bfr, Kd + (wc*32 + j*16)*QS + kk*16, QS);
                wmma::mma_sync(sacc[j], af, bfr, sacc[j]);
            }
        }
        #pragma unroll
        for (int j = 0; j < 2; j++)
            wmma::store_matrix_sync(&Sb[(wr*16)*72 + wc*32 + j*16], sacc[j], 72, wmma::mem_row_major);
        __syncthreads();

        // masked exp (no max subtraction: logits bounded, fp32 safe)
        {
            float lp = 0.f;
            #pragma unroll
            for (int j = 0; j < 16; j++) {
                int c = ec + j;
                float s = Sb[er*72 + c];
                float p = (rok && (m0 + c) < Nv) ? __expf(s) : 0.f;
                lp += p;
                Ps[er*72 + c] = __float2bfloat16(p);
            }
            lsum += lp;
        }
        __syncthreads();

        // O += P @ V
        #pragma unroll
        for (int kk = 0; kk < 4; kk++) {
            wmma::fragment<wmma::matrix_a,16,16,16,__nv_bfloat16,wmma::row_major> af;
            wmma::load_matrix_sync(af, Ps + (wr*16)*72 + kk*16, 72);
            #pragma unroll
            for (int j = 0; j < 8; j++) {
                wmma::fragment<wmma::matrix_b,16,16,16,__nv_bfloat16,wmma::row_major> bfr;
                wmma::load_matrix_sync(bfr, Vd + (kk*16)*QS + wc*128 + j*16, QS);
                wmma::mma_sync(o[j], af, bfr, o[j]);
            }
        }
        // next iteration's top sync protects stage reuse
    }

    // row-sum reduce (4 consecutive lanes per row)
    lsum += __shfl_xor_sync(0xffffffffu, lsum, 1);
    lsum += __shfl_xor_sync(0xffffffffu, lsum, 2);
    if ((t & 3) == 0) linv[er] = (lsum > 0.f) ? (1.0f / lsum) : 0.0f;
    __syncthreads();

    #pragma unroll
    for (int j = 0; j < 8; j++)
        wmma::store_matrix_sync(&Os[(wr*16)*260 + wc*128 + j*16], o[j], 260, wmma::mem_row_major);
    __syncthreads();

    for (int i = t; i < 64*256; i += 256) {
        int r = i >> 8, c = i & 255;
        if (n0 + r < Nv) {
            float vv = Os[r*260 + c] * linv[r];
            g_cat[(size_t)rg[r]*(NHEAD*DIM) + h*DIM + c] = __float2bfloat16(vv);
        }
    }
}

// ---------------- launch ----------------
extern "C" void kernel_launch(void* const* d_in, const int* in_sizes, int n_in,
                              void* d_out, int out_size)
{
    (void)in_sizes; (void)n_in; (void)out_size;
    const float* x        = (const float*)d_in[0];
    const int*   mask_idx = (const int*)  d_in[1];
    const float* spatial  = (const float*)d_in[2];
    const float* edge     = (const float*)d_in[3];
    const float* ln1_g    = (const float*)d_in[4];
    const float* ln1_b    = (const float*)d_in[5];
    const float* Wq       = (const float*)d_in[6];
    const float* bq       = (const float*)d_in[7];
    const float* Wk       = (const float*)d_in[8];
    const float* bk       = (const float*)d_in[9];
    const float* Wv       = (const float*)d_in[10];
    const float* bv       = (const float*)d_in[11];
    const float* Wo       = (const float*)d_in[12];
    const float* bo       = (const float*)d_in[13];
    const float* ln2_g    = (const float*)d_in[14];
    const float* ln2_b    = (const float*)d_in[15];
    const float* Wff      = (const float*)d_in[16];
    const float* bff      = (const float*)d_in[17];
    float* out = (float*)d_out;

    cudaFuncSetAttribute((const void*)gemm_kernel<0,1,0>,
                         cudaFuncAttributeMaxDynamicSharedMemorySize, GEMM_SMEM);
    cudaFuncSetAttribute((const void*)gemm_kernel<1,0,1>,
                         cudaFuncAttributeMaxDynamicSharedMemorySize, GEMM_SMEM);
    cudaFuncSetAttribute((const void*)gemm_kernel<1,0,0>,
                         cudaFuncAttributeMaxDynamicSharedMemorySize, GEMM_SMEM);
    cudaFuncSetAttribute((const void*)attn_kernel,
                         cudaFuncAttributeMaxDynamicSharedMemorySize, ATT_SMEM);

    __nv_bfloat16 *xln, *qkv, *cat, *xln2, *wqkv, *wo, *wff;
    float *xout;
    cudaGetSymbolAddress((void**)&xln,  g_xln);
    cudaGetSymbolAddress((void**)&wqkv, g_wqkv);
    cudaGetSymbolAddress((void**)&wo,   g_wo);
    cudaGetSymbolAddress((void**)&wff,  g_wff);
    cudaGetSymbolAddress((void**)&qkv,  g_qkv);
    cudaGetSymbolAddress((void**)&cat,  g_cat);
    cudaGetSymbolAddress((void**)&xout, g_xout);
    cudaGetSymbolAddress((void**)&xln2, g_xln2);

    // (1) mask compaction
    compact_kernel<<<1, 1024>>>(mask_idx);

    // (2) fused weight conversions
    cvt_all_kernel<<<(4*HDD + DIM*DIM)/256, 256>>>(Wq, Wk, Wv, Wo, Wff);

    // (3) LN1 -> bf16, compacted rows
    ln_kernel<1><<<NTOK, 256>>>(x, ln1_g, ln1_b, xln);

    // (4) fused QKV projection on compacted rows
    gemm_kernel<0,1,0><<<dim3(32,48), 256, GEMM_SMEM>>>(xln, wqkv, DIM,
                                                        bq, bk, bv, nullptr, nullptr, qkv);

    // (5) compact bias precompute
    bias_pre_kernel<<<dim3(16, NTOK), 256>>>(spatial, edge);

    // (6) attention (profiled launch under ncu -s 5 -c 1)
    attn_kernel<<<dim3(NHEAD, NTOK/64), 256, ATT_SMEM>>>();

    // (7) output projection + residual (masked cat rows zero-filled at load)
    gemm_kernel<1,0,1><<<dim3(32,2), 256, GEMM_SMEM>>>(cat, wo, NHEAD*DIM,
                                                       bo, nullptr, nullptr, x, xout, nullptr);

    // (8) LN2 -> bf16 (full domain)
    ln_kernel<0><<<NTOK, 256>>>(xout, ln2_g, ln2_b, xln2);

    // (9) FF + residual
    gemm_kernel<1,0,0><<<dim3(32,2), 256, GEMM_SMEM>>>(xln2, wff, DIM,
                                                       bff, nullptr, nullptr, xout, out, nullptr);
}

// round 4
// speedup vs baseline: 8.9292x; 1.0038x over previous
#include <cuda_runtime.h>
#include <cuda_bf16.h>
#include <mma.h>
#include <cstdint>

using namespace nvcuda;

#define NTOK 4096
#define DIM 256
#define NHEAD 8
#define HDD (NHEAD*DIM*DIM)
#define BSTRIDE 4128            // padded fp32 row stride of compact bias

// ---------------- scratch (device globals; no cudaMalloc allowed) ----------------
__device__ __nv_bfloat16 g_xln [NTOK*DIM];      // compacted valid rows
__device__ __nv_bfloat16 g_wqkv[3*HDD];
__device__ __nv_bfloat16 g_wo  [DIM*NHEAD*DIM];
__device__ __nv_bfloat16 g_wff [DIM*DIM];
__device__ __nv_bfloat16 g_qkv [3ULL*NHEAD*NTOK*DIM];    // compacted rows per head
__device__ __nv_bfloat16 g_cat [(size_t)NTOK*NHEAD*DIM]; // valid rows written; masked zfilled at Wo load
__device__ float         g_xout[NTOK*DIM];
__device__ __nv_bfloat16 g_xln2[NTOK*DIM];
__device__ float         g_bias[(size_t)NTOK*BSTRIDE];   // compact (spatial+edge)
__device__ int           g_nvalid;
__device__ int           g_idx [NTOK];          // compacted -> original token id
__device__ int           g_cidx[NTOK];          // original -> compacted (or -1)

// ---------------- cp.async helpers ----------------
__device__ __forceinline__ void cp16(void* dst, const void* src) {
    uint32_t d = (uint32_t)__cvta_generic_to_shared(dst);
    asm volatile("cp.async.cg.shared.global [%0], [%1], 16;\n" :: "r"(d), "l"(src));
}
__device__ __forceinline__ void cp16p(void* dst, const void* src, bool p) {
    uint32_t d = (uint32_t)__cvta_generic_to_shared(dst);
    int sz = p ? 16 : 0;
    asm volatile("cp.async.cg.shared.global [%0], [%1], 16, %2;\n" :: "r"(d), "l"(src), "r"(sz));
}
__device__ __forceinline__ void cp_commit() {
    asm volatile("cp.async.commit_group;\n");
}
__device__ __forceinline__ void cp_wait0() {
    asm volatile("cp.async.wait_group 0;\n");
}

// ---------------- mask compaction: prefix scan over 4096 mask values -------------
__global__ void compact_kernel(const int* __restrict__ mask)
{
    __shared__ int warpsum[32];
    int t = threadIdx.x;              // 1024 threads, 4 elems each
    int base = t * 4;
    int m[4], s = 0;
    #pragma unroll
    for (int i = 0; i < 4; i++) { m[i] = (mask[base+i] != 0); s += m[i]; }
    int lane = t & 31, w = t >> 5;
    int pre = s;
    #pragma unroll
    for (int o = 1; o < 32; o <<= 1) {
        int v = __shfl_up_sync(0xffffffffu, pre, o);
        if (lane >= o) pre += v;
    }
    if (lane == 31) warpsum[w] = pre;
    __syncthreads();
    if (t < 32) {
        int v = warpsum[t];
        #pragma unroll
        for (int o = 1; o < 32; o <<= 1) {
            int u = __shfl_up_sync(0xffffffffu, v, o);
            if (t >= o) v += u;
        }
        warpsum[t] = v;
    }
    __syncthreads();
    int off = pre - s + ((w > 0) ? warpsum[w-1] : 0);
    #pragma unroll
    for (int i = 0; i < 4; i++) {
        if (m[i]) { g_idx[off] = base + i; g_cidx[base+i] = off; off++; }
        else      { g_cidx[base+i] = -1; }
    }
    if (t == 0) g_nvalid = warpsum[31];
}

// ---------------- fused weight conversion fp32 -> bf16 ----------------
__global__ void cvt_all_kernel(const float* __restrict__ Wq, const float* __restrict__ Wk,
                               const float* __restrict__ Wv, const float* __restrict__ Wo,
                               const float* __restrict__ Wff)
{
    int i = blockIdx.x * 256 + threadIdx.x;
    if      (i <   HDD) g_wqkv[i] = __float2bfloat16(Wq[i]);
    else if (i < 2*HDD) g_wqkv[i] = __float2bfloat16(Wk[i -   HDD]);
    else if (i < 3*HDD) g_wqkv[i] = __float2bfloat16(Wv[i - 2*HDD]);
    else if (i < 4*HDD) g_wo [i - 3*HDD] = __float2bfloat16(Wo [i - 3*HDD]);
    else                g_wff[i - 4*HDD] = __float2bfloat16(Wff[i - 4*HDD]);
}

// ---------------- layernorm: fp32 in -> bf16 out (optionally compacted) ----------
template<int COMPACT>
__global__ void ln_kernel(const float* __restrict__ x, const float* __restrict__ g,
                          const float* __restrict__ b, __nv_bfloat16* __restrict__ out)
{
    int row = blockIdx.x;
    int orow = row;
    if (COMPACT) { orow = g_cidx[row]; if (orow < 0) return; }
    int t = threadIdx.x;
    float v = x[row*DIM + t];
    float sum = v, sq = v*v;
    #pragma unroll
    for (int o = 16; o > 0; o >>= 1) {
        sum += __shfl_xor_sync(0xffffffffu, sum, o);
        sq  += __shfl_xor_sync(0xffffffffu, sq,  o);
    }
    __shared__ float s1[8], s2[8];
    if ((t & 31) == 0) { s1[t>>5] = sum; s2[t>>5] = sq; }
    __syncthreads();
    __shared__ float smu, srstd;
    if (t == 0) {
        float S = 0.f, Q = 0.f;
        #pragma unroll
        for (int i = 0; i < 8; i++) { S += s1[i]; Q += s2[i]; }
        float m = S * (1.0f/DIM);
        smu = m;
        srstd = rsqrtf(Q * (1.0f/DIM) - m*m + 1e-5f);
    }
    __syncthreads();
    out[orow*DIM + t] = __float2bfloat16((v - smu) * srstd * g[t] + b[t]);
}

// ---------------- compact bias precompute: g_bias[i,j] = sp[gi,gj]+ed[gi,gj] -----
__global__ void bias_pre_kernel(const float* __restrict__ spatial,
                                const float* __restrict__ edge)
{
    int i = blockIdx.y;
    if (i >= g_nvalid) return;
    int j = blockIdx.x * 256 + threadIdx.x;
    if (j >= g_nvalid) return;
    int gi = g_idx[i];
    int gj = __ldg(&g_idx[j]);
    size_t off = (size_t)gi*NTOK + gj;
    g_bias[(size_t)i*BSTRIDE + j] = __ldg(&spatial[off]) + __ldg(&edge[off]);
}

// ---------------- 128x128 bf16 WMMA GEMM, 64-wide K panels, cp.async 2-stage -----
// C = A @ B^T.  EPI 0 (+COMPACT): QKV scatter (bias + q-scale, bf16 out)
//               EPI 1: bias + residual, fp32 out.  ZMASK: zero-fill masked A rows.
#define GEMM_SMEM (4*128*72*2 > 128*132*4 ? 4*128*72*2 : 128*132*4)   // 73728

template<int EPI, int COMPACT, int ZMASK>
__global__ void gemm_kernel(const __nv_bfloat16* __restrict__ A,
                            const __nv_bfloat16* __restrict__ B,
                            int K,
                            const float* __restrict__ b0,
                            const float* __restrict__ b1,
                            const float* __restrict__ b2,
                            const float* __restrict__ res,
                            float* __restrict__ outf,
                            __nv_bfloat16* __restrict__ outb)
{
    int bm = blockIdx.x * 128;
    if (COMPACT && bm >= g_nvalid) return;

    extern __shared__ char smem[];
    __nv_bfloat16* As = (__nv_bfloat16*)smem;          // 2 stages [128][72]
    __nv_bfloat16* Bs = As + 2*128*72;                 // 2 stages [128][72]
    float* Cs = (float*)smem;                          // [128][132] alias

    int bn = blockIdx.y * 128;
    int t = threadIdx.x;
    int w = t >> 5;
    int wr = w & 3, wc = w >> 2;   // 4x2 warp grid, each warp 32x64

    // per-thread chunk rows (constant over panels): id = t + k*256, row=id>>3
    bool pm[4];
    #pragma unroll
    for (int k = 0; k < 4; k++) {
        int r = (t + k*256) >> 3;
        pm[k] = !ZMASK || (g_cidx[bm + r] >= 0);
    }

    wmma::fragment<wmma::accumulator,16,16,16,float> acc[2][4];
    #pragma unroll
    for (int i = 0; i < 2; i++)
        #pragma unroll
        for (int j = 0; j < 4; j++)
            wmma::fill_fragment(acc[i][j], 0.0f);

    int nP = K >> 6;

    auto prefetch = [&](int p, int st) {
        const __nv_bfloat16* Ap = A + (size_t)bm*K + p*64;
        const __nv_bfloat16* Bp = B + (size_t)bn*K + p*64;
        __nv_bfloat16* Ad = As + st*128*72;
        __nv_bfloat16* Bd = Bs + st*128*72;
        #pragma unroll
        for (int k = 0; k < 4; k++) {
            int id = t + k*256;
            int r = id >> 3, c = (id & 7) << 3;
            cp16p(Ad + r*72 + c, Ap + (size_t)r*K + c, pm[k]);
            cp16 (Bd + r*72 + c, Bp + (size_t)r*K + c);
        }
        cp_commit();
    };

    prefetch(0, 0);
    for (int p = 0; p < nP; p++) {
        cp_wait0();
        __syncthreads();
        if (p + 1 < nP) prefetch(p + 1, (p + 1) & 1);
        int st = p & 1;
        __nv_bfloat16* Ad = As + st*128*72;
        __nv_bfloat16* Bd = Bs + st*128*72;
        #pragma unroll
        for (int kk = 0; kk < 4; kk++) {
            wmma::fragment<wmma::matrix_a,16,16,16,__nv_bfloat16,wmma::row_major> af[2];
            #pragma unroll
            for (int i = 0; i < 2; i++)
                wmma::load_matrix_sync(af[i], Ad + (wr*32 + i*16)*72 + kk*16, 72);
            #pragma unroll
            for (int j = 0; j < 4; j++) {
                wmma::fragment<wmma::matrix_b,16,16,16,__nv_bfloat16,wmma::col_major> bfr;
                wmma::load_matrix_sync(bfr, Bd + (wc*64 + j*16)*72 + kk*16, 72);
                #pragma unroll
                for (int i = 0; i < 2; i++)
                    wmma::mma_sync(acc[i][j], af[i], bfr, acc[i][j]);
            }
        }
        __syncthreads();
    }

    #pragma unroll
    for (int i = 0; i < 2; i++)
        #pragma unroll
        for (int j = 0; j < 4; j++)
            wmma::store_matrix_sync(&Cs[(wr*32 + i*16)*132 + wc*64 + j*16], acc[i][j],
                                    132, wmma::mem_row_major);
    __syncthreads();

    for (int idx = t; idx < 128*128; idx += 256) {
        int r = idx >> 7, c = idx & 127;
        int n = bm + r, cc = bn + c;
        float v = Cs[r*132 + c];
        if (EPI == 0) {
            int which = cc >> 11;               // 0=q, 1=k, 2=v
            const float* bp = (which == 0) ? b0 : (which == 1) ? b1 : b2;
            v += bp[cc & 2047];
            if (which == 0) v *= 0.0625f;       // 1/sqrt(D), D=256
            int h = (cc >> 8) & 7;
            int e = cc & 255;
            outb[((size_t)which*NHEAD + h)*NTOK*DIM + (size_t)n*DIM + e] = __float2bfloat16(v);
        } else {
            v += b0[cc] + res[(size_t)n*DIM + cc];
            outf[(size_t)n*DIM + cc] = v;
        }
    }
}

// ---------------- fused biased attention, compacted, cp.async 2-stage pipeline ---
// grid: (NHEAD, NTOK/64). Each block: 64 compacted query rows of one head.
// dyn smem layout (bytes):
//  Qs [64][264] bf16     @ 0       33792
//  Ks 2x[64][264] bf16   @ 33792   67584   (epilogue alias: Os [64][260] f32)
//  Vs 2x[64][264] bf16   @ 101376  67584
//  Bs 2x[64][68]  f32    @ 168960  34816
//  Sb [64][72]    f32    @ 203776  18432
//  Ps [64][72]    bf16   @ 222208   9216
//  rg [64] int           @ 231424    256
//  linv [64] f32         @ 231680    256      total 231936
#define ATT_SMEM 231936
#define QS 264

__global__ void attn_kernel()
{
    int Nv = g_nvalid;
    int n0 = blockIdx.y * 64;
    if (n0 >= Nv) return;

    extern __shared__ char smem[];
    __nv_bfloat16* Qs = (__nv_bfloat16*)smem;
    __nv_bfloat16* Ks = (__nv_bfloat16*)(smem + 33792);
    __nv_bfloat16* Vs = (__nv_bfloat16*)(smem + 101376);
    float*         Bs = (float*)        (smem + 168960);
    float*         Sb = (float*)        (smem + 203776);
    __nv_bfloat16* Ps = (__nv_bfloat16*)(smem + 222208);
    int*           rg = (int*)          (smem + 231424);
    float*         linv = (float*)      (smem + 231680);
    float*         Os = (float*)Ks;                      // epilogue alias [64][260]

    int h  = blockIdx.x;
    int t  = threadIdx.x;
    int w  = t >> 5;
    int wr = w & 3, wc = w >> 2;

    const __nv_bfloat16* qh = g_qkv + (size_t)h*NTOK*DIM;
    const __nv_bfloat16* kh = g_qkv + (size_t)(NHEAD   + h)*NTOK*DIM;
    const __nv_bfloat16* vh = g_qkv + (size_t)(2*NHEAD + h)*NTOK*DIM;

    int mend = (Nv + 63) & ~63;
    int T = mend >> 6;

    auto prefetch = [&](int m, int st) {
        int m0 = m << 6;
        __nv_bfloat16* Kd = Ks + st*64*QS;
        __nv_bfloat16* Vd = Vs + st*64*QS;
        float*         Bd = Bs + st*64*68;
        #pragma unroll
        for (int k = 0; k < 8; k++) {
            int id = t + k*256;
            int r = id >> 5, c = (id & 31) << 3;
            cp16(Kd + r*QS + c, kh + (size_t)(m0+r)*DIM + c);
            cp16(Vd + r*QS + c, vh + (size_t)(m0+r)*DIM + c);
        }
        #pragma unroll
        for (int k = 0; k < 4; k++) {
            int id = t + k*256;
            int r = id >> 4, c = (id & 15) << 2;
            cp16(Bd + r*68 + c, g_bias + (size_t)(n0+r)*BSTRIDE + m0 + c);
        }
        cp_commit();
    };

    // Q + first tile prefetch (one group)
    #pragma unroll
    for (int k = 0; k < 8; k++) {
        int id = t + k*256;
        int r = id >> 5, c = (id & 31) << 3;
        cp16(Qs + r*QS + c, qh + (size_t)(n0+r)*DIM + c);
    }
    if (t < 64) rg[t] = g_idx[n0 + t];
    prefetch(0, 0);

    wmma::fragment<wmma::accumulator,16,16,16,float> o[8];
    #pragma unroll
    for (int j = 0; j < 8; j++) wmma::fill_fragment(o[j], 0.0f);

    float lsum = 0.f;
    int er = t >> 2;            // exp row (4 threads/row)
    int ec = (t & 3) << 4;      // 16 cols per thread
    bool rok = (n0 + er) < Nv;

    #pragma unroll 1
    for (int m = 0; m < T; m++) {
        cp_wait0();
        __syncthreads();                        // stage m ready; all done with m-1
        if (m + 1 < T) prefetch(m + 1, (m + 1) & 1);
        int st = m & 1;
        int m0 = m << 6;
        __nv_bfloat16* Kd = Ks + st*64*QS;
        __nv_bfloat16* Vd = Vs + st*64*QS;
        float*         Bd = Bs + st*64*68;

        // S = (q/16) K^T + bias (bias preloaded as accumulator)
        wmma::fragment<wmma::accumulator,16,16,16,float> sacc[2];
        #pragma unroll
        for (int j = 0; j < 2; j++)
            wmma::load_matrix_sync(sacc[j], Bd + (wr*16)*68 + wc*32 + j*16, 68, wmma::mem_row_major);
        #pragma unroll
        for (int kk = 0; kk < 16; kk++) {
            wmma::fragment<wmma::matrix_a,16,16,16,__nv_bfloat16,wmma::row_major> af;
            wmma::load_matrix_sync(af, Qs + (wr*16)*QS + kk*16, QS);
            #pragma unroll
            for (int j = 0; j < 2; j++) {
                wmma::fragment<wmma::matrix_b,16,16,16,__nv_bfloat16,wmma::col_major> bfr;
                wmma::load_matrix_sync(bfr, Kd + (wc*32 + j*16)*QS + kk*16, QS);
                wmma::mma_sync(sacc[j], af, bfr, sacc[j]);
            }
        }
        #pragma unroll
        for (int j = 0; j < 2; j++)
            wmma::store_matrix_sync(&Sb[(wr*16)*72 + wc*32 + j*16], sacc[j], 72, wmma::mem_row_major);
        __syncthreads();

        // masked exp (no max subtraction: logits bounded, fp32 safe)
        {
            float lp = 0.f;
            #pragma unroll
            for (int j = 0; j < 16; j++) {
                int c = ec + j;
                float s = Sb[er*72 + c];
                float p = (rok && (m0 + c) < Nv) ? __expf(s) : 0.f;
                lp += p;
                Ps[er*72 + c] = __float2bfloat16(p);
            }
            lsum += lp;
        }
        __syncthreads();

        // O += P @ V
        #pragma unroll
        for (int kk = 0; kk < 4; kk++) {
            wmma::fragment<wmma::matrix_a,16,16,16,__nv_bfloat16,wmma::row_major> af;
            wmma::load_matrix_sync(af, Ps + (wr*16)*72 + kk*16, 72);
            #pragma unroll
            for (int j = 0; j < 8; j++) {
                wmma::fragment<wmma::matrix_b,16,16,16,__nv_bfloat16,wmma::row_major> bfr;
                wmma::load_matrix_sync(bfr, Vd + (kk*16)*QS + wc*128 + j*16, QS);
                wmma::mma_sync(o[j], af, bfr, o[j]);
            }
        }
        // next iteration's top sync protects stage reuse
    }

    // row-sum reduce (4 consecutive lanes per row)
    lsum += __shfl_xor_sync(0xffffffffu, lsum, 1);
    lsum += __shfl_xor_sync(0xffffffffu, lsum, 2);
    if ((t & 3) == 0) linv[er] = (lsum > 0.f) ? (1.0f / lsum) : 0.0f;
    __syncthreads();

    #pragma unroll
    for (int j = 0; j < 8; j++)
        wmma::store_matrix_sync(&Os[(wr*16)*260 + wc*128 + j*16], o[j], 260, wmma::mem_row_major);
    __syncthreads();

    for (int i = t; i < 64*256; i += 256) {
        int r = i >> 8, c = i & 255;
        if (n0 + r < Nv) {
            float vv = Os[r*260 + c] * linv[r];
            g_cat[(size_t)rg[r]*(NHEAD*DIM) + h*DIM + c] = __float2bfloat16(vv);
        }
    }
}

// ---------------- launch ----------------
extern "C" void kernel_launch(void* const* d_in, const int* in_sizes, int n_in,
                              void* d_out, int out_size)
{
    (void)in_sizes; (void)n_in; (void)out_size;
    const float* x        = (const float*)d_in[0];
    const int*   mask_idx = (const int*)  d_in[1];
    const float* spatial  = (const float*)d_in[2];
    const float* edge     = (const float*)d_in[3];
    const float* ln1_g    = (const float*)d_in[4];
    const float* ln1_b    = (const float*)d_in[5];
    const float* Wq       = (const float*)d_in[6];
    const float* bq       = (const float*)d_in[7];
    const float* Wk       = (const float*)d_in[8];
    const float* bk       = (const float*)d_in[9];
    const float* Wv       = (const float*)d_in[10];
    const float* bv       = (const float*)d_in[11];
    const float* Wo       = (const float*)d_in[12];
    const float* bo       = (const float*)d_in[13];
    const float* ln2_g    = (const float*)d_in[14];
    const float* ln2_b    = (const float*)d_in[15];
    const float* Wff      = (const float*)d_in[16];
    const float* bff      = (const float*)d_in[17];
    float* out = (float*)d_out;

    cudaFuncSetAttribute((const void*)gemm_kernel<0,1,0>,
                         cudaFuncAttributeMaxDynamicSharedMemorySize, GEMM_SMEM);
    cudaFuncSetAttribute((const void*)gemm_kernel<1,0,1>,
                         cudaFuncAttributeMaxDynamicSharedMemorySize, GEMM_SMEM);
    cudaFuncSetAttribute((const void*)gemm_kernel<1,0,0>,
                         cudaFuncAttributeMaxDynamicSharedMemorySize, GEMM_SMEM);
    cudaFuncSetAttribute((const void*)attn_kernel,
                         cudaFuncAttributeMaxDynamicSharedMemorySize, ATT_SMEM);

    __nv_bfloat16 *xln, *qkv, *cat, *xln2, *wqkv, *wo, *wff;
    float *xout;
    cudaGetSymbolAddress((void**)&xln,  g_xln);
    cudaGetSymbolAddress((void**)&wqkv, g_wqkv);
    cudaGetSymbolAddress((void**)&wo,   g_wo);
    cudaGetSymbolAddress((void**)&wff,  g_wff);
    cudaGetSymbolAddress((void**)&qkv,  g_qkv);
    cudaGetSymbolAddress((void**)&cat,  g_cat);
    cudaGetSymbolAddress((void**)&xout, g_xout);
    cudaGetSymbolAddress((void**)&xln2, g_xln2);

    // (1) mask compaction
    compact_kernel<<<1, 1024>>>(mask_idx);

    // (2) fused weight conversions
    cvt_all_kernel<<<(4*HDD + DIM*DIM)/256, 256>>>(Wq, Wk, Wv, Wo, Wff);

    // (3) LN1 -> bf16, compacted rows
    ln_kernel<1><<<NTOK, 256>>>(x, ln1_g, ln1_b, xln);

    // (4) fused QKV projection on compacted rows
    gemm_kernel<0,1,0><<<dim3(32,48), 256, GEMM_SMEM>>>(xln, wqkv, DIM,
                                                        bq, bk, bv, nullptr, nullptr, qkv);

    // (5) compact bias precompute
    bias_pre_kernel<<<dim3(16, NTOK), 256>>>(spatial, edge);

    // (6) attention (profiled launch under ncu -s 5 -c 1)
    attn_kernel<<<dim3(NHEAD, NTOK/64), 256, ATT_SMEM>>>();

    // (7) output projection + residual (masked cat rows zero-filled at load)
    gemm_kernel<1,0,1><<<dim3(32,2), 256, GEMM_SMEM>>>(cat, wo, NHEAD*DIM,
                                                       bo, nullptr, nullptr, x, xout, nullptr);

    // (8) LN2 -> bf16 (full domain)
    ln_kernel<0><<<NTOK, 256>>>(xout, ln2_g, ln2_b, xln2);

    // (9) FF + residual
    gemm_kernel<1,0,0><<<dim3(32,2), 256, GEMM_SMEM>>>(xln2, wff, DIM,
                                                       bff, nullptr, nullptr, xout, out, nullptr);
}